// round 1
// baseline (speedup 1.0000x reference)
#include <cuda_runtime.h>
#include <cuda_bf16.h>
#include <math.h>

// Problem constants
#define BB   2
#define SS   2048
#define HIDD 4096
#define NHH  32
#define NKVV 8
#define HDD  128
#define GG   4

// Scratch (device globals: allocation-free rule)
__device__ float g_Q[(size_t)BB * NHH * SS * HDD];    // [B, NH, S, HD]   64 MB
__device__ float g_K[(size_t)BB * NKVV * SS * HDD];   // [B, NKV, S, HD]  16 MB
__device__ float g_V[(size_t)BB * NKVV * SS * HDD];   // [B, NKV, S, HD]  16 MB
__device__ float g_AO[(size_t)BB * SS * HIDD];        // [B, S, HID]      64 MB

// ---------------------------------------------------------------------------
// NT GEMM: Y[m,n] = sum_k X[m,k] * W[n,k]
// MODE 0: Y row-major [M,N].  MODE 1: Y scattered to [B, H, S, HD] head layout.
// src_sel: 0 -> Xext, 1 -> g_AO.   dst_sel: 0 -> Yext, 1 -> g_Q, 2 -> g_K, 3 -> g_V.
// BM=BN=64, BK=16, 256 threads, 4x4 micro-tile per thread.
// ---------------------------------------------------------------------------
template <int MODE>
__global__ void __launch_bounds__(256) gemm_nt_kernel(
    const float* __restrict__ Xext, const float* __restrict__ W,
    float* __restrict__ Yext, int M, int N, int K, int H,
    int src_sel, int dst_sel)
{
    __shared__ __align__(16) float Xs[16][64];
    __shared__ __align__(16) float Ws[16][64];

    const float* X = (src_sel == 1) ? g_AO : Xext;
    float* Y;
    if (dst_sel == 1)      Y = g_Q;
    else if (dst_sel == 2) Y = g_K;
    else if (dst_sel == 3) Y = g_V;
    else                   Y = Yext;

    const int bm = blockIdx.y * 64;
    const int bn = blockIdx.x * 64;
    const int tid = threadIdx.x;
    const int tx = tid & 15;          // -> n micro
    const int ty = tid >> 4;          // -> m micro
    const int lm = tid >> 2;          // 0..63 row for tile loads
    const int lk = (tid & 3) << 2;    // 0,4,8,12 k base for tile loads

    float acc[4][4];
#pragma unroll
    for (int i = 0; i < 4; i++)
#pragma unroll
        for (int j = 0; j < 4; j++) acc[i][j] = 0.0f;

    const float* Xp = X + (size_t)(bm + lm) * K + lk;
    const float* Wp = W + (size_t)(bn + lm) * K + lk;

    for (int k0 = 0; k0 < K; k0 += 16) {
        float4 xv = *(const float4*)(Xp + k0);
        float4 wv = *(const float4*)(Wp + k0);
        Xs[lk + 0][lm] = xv.x; Xs[lk + 1][lm] = xv.y;
        Xs[lk + 2][lm] = xv.z; Xs[lk + 3][lm] = xv.w;
        Ws[lk + 0][lm] = wv.x; Ws[lk + 1][lm] = wv.y;
        Ws[lk + 2][lm] = wv.z; Ws[lk + 3][lm] = wv.w;
        __syncthreads();

#pragma unroll
        for (int k = 0; k < 16; k++) {
            float4 a = *(const float4*)&Xs[k][ty << 2];
            float4 b = *(const float4*)&Ws[k][tx << 2];
            acc[0][0] += a.x * b.x; acc[0][1] += a.x * b.y; acc[0][2] += a.x * b.z; acc[0][3] += a.x * b.w;
            acc[1][0] += a.y * b.x; acc[1][1] += a.y * b.y; acc[1][2] += a.y * b.z; acc[1][3] += a.y * b.w;
            acc[2][0] += a.z * b.x; acc[2][1] += a.z * b.y; acc[2][2] += a.z * b.z; acc[2][3] += a.z * b.w;
            acc[3][0] += a.w * b.x; acc[3][1] += a.w * b.y; acc[3][2] += a.w * b.z; acc[3][3] += a.w * b.w;
        }
        __syncthreads();
    }

#pragma unroll
    for (int i = 0; i < 4; i++) {
        const int m = bm + (ty << 2) + i;
#pragma unroll
        for (int j = 0; j < 4; j++) {
            const int n = bn + (tx << 2) + j;
            if (MODE == 0) {
                Y[(size_t)m * N + n] = acc[i][j];
            } else {
                const int b = m / SS, s = m % SS;
                const int h = n / HDD, d = n % HDD;
                Y[(((size_t)b * H + h) * SS + s) * HDD + d] = acc[i][j];
            }
        }
    }
}

// ---------------------------------------------------------------------------
// In-place RoPE on [B, H, S, HD].  WHICH 0 -> g_Q (H=NH), 1 -> g_K (H=NKV).
// Llama duplicated-half convention: out[d] = x[d]*cos - x[d+64]*sin,
//                                   out[d+64] = x[d+64]*cos + x[d]*sin.
// ---------------------------------------------------------------------------
template <int WHICH>
__global__ void rope_kernel()
{
    const int s = blockIdx.x, h = blockIdx.y, b = blockIdx.z;
    const int d = threadIdx.x;  // 0..63
    const int H = WHICH ? NKVV : NHH;
    float* P = WHICH ? g_K : g_Q;
    const size_t base = (((size_t)b * H + h) * SS + s) * HDD;

    const double inv = pow(10000.0, -(double)d / 64.0);
    const float f = (float)((double)s * inv);
    float sn, c;
    sincosf(f, &sn, &c);

    const float x1 = P[base + d];
    const float x2 = P[base + d + 64];
    P[base + d]      = x1 * c - x2 * sn;
    P[base + d + 64] = x2 * c + x1 * sn;
}

// ---------------------------------------------------------------------------
// Flash attention (fp32, causal, GQA), streaming softmax.
// Block: (q-tile 32, head, batch). 256 threads.
// Scores phase: tx -> 2 keys, ty -> 2 queries (32x32 scores / 256 thr = 4 each).
// PV phase:     tx -> 8 dims, ty -> 2 queries (32x128 out / 256 thr = 16 accum).
// K stored transposed in smem (stride 33) -> conflict-free score loads.
// K and V share one smem buffer (4224 floats each way).
// ---------------------------------------------------------------------------
__global__ void __launch_bounds__(256) attn_kernel()
{
    __shared__ __align__(16) float Qs[32 * 132];
    __shared__ __align__(16) float KVs[4224];      // Kst[128][33] or Vs[32][132]
    __shared__ __align__(16) float Ps[32 * 33];
    __shared__ float row_m[32], row_l[32], row_alpha[32];

    const int qt = blockIdx.x;
    const int h  = blockIdx.y;
    const int b  = blockIdx.z;
    const int kvh = h / GG;
    const int tid = threadIdx.x;
    const int tx = tid & 15;
    const int ty = tid >> 4;
    const int q0 = ty * 2;

    const float* Qg = g_Q + (((size_t)b * NHH + h) * SS + (size_t)qt * 32) * HDD;
    const float* Kg = g_K + (((size_t)b * NKVV + kvh) * SS) * HDD;
    const float* Vg = g_V + (((size_t)b * NKVV + kvh) * SS) * HDD;

    // Load Q tile 32x128
    for (int i = tid; i < 1024; i += 256) {
        const int r = i >> 5;
        const int c = (i & 31) << 2;
        float4 v = *(const float4*)(Qg + (size_t)r * HDD + c);
        *(float4*)&Qs[r * 132 + c] = v;
    }
    if (tid < 32) { row_m[tid] = -3.0e38f; row_l[tid] = 0.0f; }

    float O[2][8];
#pragma unroll
    for (int i = 0; i < 2; i++)
#pragma unroll
        for (int c = 0; c < 8; c++) O[i][c] = 0.0f;

    const float scale = 0.08838834764831845f;  // 1/sqrt(128)
    const int ntiles = qt + 1;                 // causal: kv tiles 0..qt

    for (int t = 0; t < ntiles; t++) {
        const int kv0 = t * 32;
        __syncthreads();  // previous PV reads of KVs/Ps complete

        // Load K tile transposed: KVs[d*33 + kj]
        for (int i = tid; i < 1024; i += 256) {
            const int r = i >> 5;         // kj
            const int c = (i & 31) << 2;  // d
            float4 v = *(const float4*)(Kg + (size_t)(kv0 + r) * HDD + c);
            KVs[(c + 0) * 33 + r] = v.x;
            KVs[(c + 1) * 33 + r] = v.y;
            KVs[(c + 2) * 33 + r] = v.z;
            KVs[(c + 3) * 33 + r] = v.w;
        }
        __syncthreads();

        // Scores: 2 queries x 2 keys per thread
        float sc[2][2] = {{0.f, 0.f}, {0.f, 0.f}};
        const int kl = tx * 2;
#pragma unroll 4
        for (int d = 0; d < HDD; d++) {
            const float qv0 = Qs[(q0 + 0) * 132 + d];
            const float qv1 = Qs[(q0 + 1) * 132 + d];
            const float k0v = KVs[d * 33 + kl + 0];
            const float k1v = KVs[d * 33 + kl + 1];
            sc[0][0] += qv0 * k0v; sc[0][1] += qv0 * k1v;
            sc[1][0] += qv1 * k0v; sc[1][1] += qv1 * k1v;
        }

        // Causal mask + scale, then row-max across the 16-lane tx group
        float mx[2];
#pragma unroll
        for (int i = 0; i < 2; i++) {
            const int sq = qt * 32 + q0 + i;
#pragma unroll
            for (int j = 0; j < 2; j++) {
                const int sk = kv0 + kl + j;
                sc[i][j] = (sk <= sq) ? sc[i][j] * scale : -3.0e38f;
            }
            mx[i] = fmaxf(sc[i][0], sc[i][1]);
            for (int ofs = 1; ofs < 16; ofs <<= 1)
                mx[i] = fmaxf(mx[i], __shfl_xor_sync(0xffffffffu, mx[i], ofs));
        }
        if (tx == 0) {
#pragma unroll
            for (int i = 0; i < 2; i++) {
                const float mo = row_m[q0 + i];
                const float mn = fmaxf(mo, mx[i]);
                row_m[q0 + i] = mn;
                row_alpha[q0 + i] = __expf(mo - mn);
            }
        }
        __syncthreads();

        // Probabilities + row sums
        float psum[2];
#pragma unroll
        for (int i = 0; i < 2; i++) {
            const float mn = row_m[q0 + i];
            const float p0 = __expf(sc[i][0] - mn);
            const float p1 = __expf(sc[i][1] - mn);
            Ps[(q0 + i) * 33 + kl + 0] = p0;
            Ps[(q0 + i) * 33 + kl + 1] = p1;
            psum[i] = p0 + p1;
            for (int ofs = 1; ofs < 16; ofs <<= 1)
                psum[i] += __shfl_xor_sync(0xffffffffu, psum[i], ofs);
        }
        if (tx == 0) {
#pragma unroll
            for (int i = 0; i < 2; i++)
                row_l[q0 + i] = row_l[q0 + i] * row_alpha[q0 + i] + psum[i];
        }
        __syncthreads();  // score-phase KVs reads done; Ps/row_* published

        // Load V tile: KVs[kj*132 + d]
        for (int i = tid; i < 1024; i += 256) {
            const int r = i >> 5;
            const int c = (i & 31) << 2;
            float4 v = *(const float4*)(Vg + (size_t)(kv0 + r) * HDD + c);
            *(float4*)&KVs[r * 132 + c] = v;
        }
        __syncthreads();

        // PV: tx -> 8 output dims, ty -> same 2 query rows
        {
            const int dq = tx * 8;
            const float a0 = row_alpha[q0 + 0];
            const float a1 = row_alpha[q0 + 1];
#pragma unroll
            for (int c = 0; c < 8; c++) { O[0][c] *= a0; O[1][c] *= a1; }
#pragma unroll 4
            for (int kj = 0; kj < 32; kj++) {
                const float p0 = Ps[(q0 + 0) * 33 + kj];
                const float p1 = Ps[(q0 + 1) * 33 + kj];
                const float* vrow = &KVs[kj * 132 + dq];
                const float4 v0 = *(const float4*)(vrow);
                const float4 v1 = *(const float4*)(vrow + 4);
                O[0][0] += p0 * v0.x; O[0][1] += p0 * v0.y; O[0][2] += p0 * v0.z; O[0][3] += p0 * v0.w;
                O[0][4] += p0 * v1.x; O[0][5] += p0 * v1.y; O[0][6] += p0 * v1.z; O[0][7] += p0 * v1.w;
                O[1][0] += p1 * v0.x; O[1][1] += p1 * v0.y; O[1][2] += p1 * v0.z; O[1][3] += p1 * v0.w;
                O[1][4] += p1 * v1.x; O[1][5] += p1 * v1.y; O[1][6] += p1 * v1.z; O[1][7] += p1 * v1.w;
            }
        }
    }

    // Epilogue: normalize and write to AO[b, s, h*HD + d]
    const float l0 = 1.0f / row_l[q0 + 0];
    const float l1 = 1.0f / row_l[q0 + 1];
    float* AOp = g_AO + ((size_t)b * SS + (size_t)qt * 32) * HIDD + (size_t)h * HDD + tx * 8;
#pragma unroll
    for (int c = 0; c < 8; c++) {
        AOp[(size_t)(q0 + 0) * HIDD + c] = O[0][c] * l0;
        AOp[(size_t)(q0 + 1) * HIDD + c] = O[1][c] * l1;
    }
}

// ---------------------------------------------------------------------------
extern "C" void kernel_launch(void* const* d_in, const int* in_sizes, int n_in,
                              void* d_out, int out_size)
{
    (void)in_sizes; (void)n_in; (void)out_size;
    const float* hs = (const float*)d_in[0];
    const float* Wq = (const float*)d_in[1];
    const float* Wk = (const float*)d_in[2];
    const float* Wv = (const float*)d_in[3];
    const float* Wo = (const float*)d_in[4];
    float* out = (float*)d_out;

    const int M = BB * SS;  // 4096
    dim3 blk(256);

    // QKV projections (write directly into head-major scratch)
    gemm_nt_kernel<1><<<dim3((NHH * HDD) / 64, M / 64), blk>>>(
        hs, Wq, nullptr, M, NHH * HDD, HIDD, NHH, 0, 1);
    gemm_nt_kernel<1><<<dim3((NKVV * HDD) / 64, M / 64), blk>>>(
        hs, Wk, nullptr, M, NKVV * HDD, HIDD, NKVV, 0, 2);
    gemm_nt_kernel<1><<<dim3((NKVV * HDD) / 64, M / 64), blk>>>(
        hs, Wv, nullptr, M, NKVV * HDD, HIDD, NKVV, 0, 3);

    // RoPE in place on Q and K
    rope_kernel<0><<<dim3(SS, NHH, BB), 64>>>();
    rope_kernel<1><<<dim3(SS, NKVV, BB), 64>>>();

    // Causal GQA flash attention -> g_AO [B, S, HID]
    attn_kernel<<<dim3(SS / 32, NHH, BB), 256>>>();

    // Output projection: out = AO @ Wo^T
    gemm_nt_kernel<0><<<dim3(HIDD / 64, M / 64), blk>>>(
        nullptr, Wo, out, M, HIDD, HIDD, 0, 1, 0);
}

// round 2
// speedup vs baseline: 2.6089x; 2.6089x over previous
#include <cuda_runtime.h>
#include <cuda_bf16.h>
#include <math.h>
#include <stdint.h>

// Problem constants
#define BB   2
#define SS   2048
#define HIDD 4096
#define NHH  32
#define NKVV 8
#define HDD  128
#define GG   4

// Scratch (device globals: allocation-free rule)
__device__ float g_Q[(size_t)BB * NHH * SS * HDD];    // [B, NH, S, HD]
__device__ float g_K[(size_t)BB * NKVV * SS * HDD];   // [B, NKV, S, HD]
__device__ float g_V[(size_t)BB * NKVV * SS * HDD];   // [B, NKV, S, HD]
__device__ float g_AO[(size_t)BB * SS * HIDD];        // [B, S, HID]

// ---------------------------------------------------------------------------
// MMA helpers
// ---------------------------------------------------------------------------
__device__ __forceinline__ uint32_t sptr(const void* p) {
    return (uint32_t)__cvta_generic_to_shared(p);
}
__device__ __forceinline__ void ldm4(uint32_t* r, uint32_t a) {
    asm volatile("ldmatrix.sync.aligned.m8n8.x4.shared.b16 {%0,%1,%2,%3}, [%4];\n"
        : "=r"(r[0]), "=r"(r[1]), "=r"(r[2]), "=r"(r[3]) : "r"(a));
}
__device__ __forceinline__ void ldm4t(uint32_t* r, uint32_t a) {
    asm volatile("ldmatrix.sync.aligned.m8n8.x4.trans.shared.b16 {%0,%1,%2,%3}, [%4];\n"
        : "=r"(r[0]), "=r"(r[1]), "=r"(r[2]), "=r"(r[3]) : "r"(a));
}
__device__ __forceinline__ void mma_bf16(float* c, const uint32_t* a, uint32_t b0, uint32_t b1) {
    asm volatile(
        "mma.sync.aligned.m16n8k16.row.col.f32.bf16.bf16.f32 "
        "{%0,%1,%2,%3}, {%4,%5,%6,%7}, {%8,%9}, {%0,%1,%2,%3};\n"
        : "+f"(c[0]), "+f"(c[1]), "+f"(c[2]), "+f"(c[3])
        : "r"(a[0]), "r"(a[1]), "r"(a[2]), "r"(a[3]), "r"(b0), "r"(b1));
}
__device__ __forceinline__ void split2(float x, __nv_bfloat16& h, __nv_bfloat16& l) {
    h = __float2bfloat16(x);
    l = __float2bfloat16(x - __bfloat162float(h));
}

// ---------------------------------------------------------------------------
// NT GEMM via bf16-split mma: Y[m,n] = sum_k X[m,k] * W[n,k]
// Block tile 128(M) x 64(N), K-step 32.  256 threads = 8 warps, 4(M) x 2(N),
// each warp 32x32 = 2 m16-tiles x 4 n8-tiles.  3 MMAs per tile pair (hh,hl,lh).
// MODE 0: row-major out.  MODE 1: scatter to [B,H,S,HD].
// ---------------------------------------------------------------------------
#define LDP 40  // bf16 row stride in smem for 32-wide k tiles

template <int MODE>
__global__ void __launch_bounds__(256) gemm_mma(
    const float* __restrict__ Xext, const float* __restrict__ W,
    float* __restrict__ Yext, int M, int N, int K, int H,
    int src_sel, int dst_sel)
{
    __shared__ __align__(16) __nv_bfloat16 Xh[128 * LDP];
    __shared__ __align__(16) __nv_bfloat16 Xl[128 * LDP];
    __shared__ __align__(16) __nv_bfloat16 Wh[64 * LDP];
    __shared__ __align__(16) __nv_bfloat16 Wl[64 * LDP];

    const float* X = (src_sel == 1) ? g_AO : Xext;
    float* Y;
    if (dst_sel == 1)      Y = g_Q;
    else if (dst_sel == 2) Y = g_K;
    else if (dst_sel == 3) Y = g_V;
    else                   Y = Yext;

    const int bm = blockIdx.y * 128;
    const int bn = blockIdx.x * 64;
    const int tid = threadIdx.x;
    const int lane = tid & 31;
    const int wid = tid >> 5;
    const int wm = wid & 3;        // 0..3 -> 32-row band
    const int wn = wid >> 2;       // 0..1 -> 32-col band

    float acc[2][4][4];
#pragma unroll
    for (int i = 0; i < 2; i++)
#pragma unroll
        for (int j = 0; j < 4; j++)
#pragma unroll
            for (int e = 0; e < 4; e++) acc[i][j][e] = 0.0f;

    const int arow = wm * 32 + (lane & 15);
    const int acol = (lane >> 4) << 3;
    const int brow = (lane & 7) + ((lane & 16) ? 8 : 0);
    const int bc8  = (lane & 8) ? 8 : 0;

    for (int k0 = 0; k0 < K; k0 += 32) {
        // Load + split X tile 128x32
#pragma unroll
        for (int i = 0; i < 4; i++) {
            const int lin = tid + i * 256;
            const int r = lin >> 3, c = (lin & 7) << 2;
            float4 v = *(const float4*)(X + (size_t)(bm + r) * K + k0 + c);
            __nv_bfloat16 hh, ll;
            split2(v.x, hh, ll); Xh[r * LDP + c + 0] = hh; Xl[r * LDP + c + 0] = ll;
            split2(v.y, hh, ll); Xh[r * LDP + c + 1] = hh; Xl[r * LDP + c + 1] = ll;
            split2(v.z, hh, ll); Xh[r * LDP + c + 2] = hh; Xl[r * LDP + c + 2] = ll;
            split2(v.w, hh, ll); Xh[r * LDP + c + 3] = hh; Xl[r * LDP + c + 3] = ll;
        }
        // Load + split W tile 64x32
#pragma unroll
        for (int i = 0; i < 2; i++) {
            const int lin = tid + i * 256;
            const int r = lin >> 3, c = (lin & 7) << 2;
            float4 v = *(const float4*)(W + (size_t)(bn + r) * K + k0 + c);
            __nv_bfloat16 hh, ll;
            split2(v.x, hh, ll); Wh[r * LDP + c + 0] = hh; Wl[r * LDP + c + 0] = ll;
            split2(v.y, hh, ll); Wh[r * LDP + c + 1] = hh; Wl[r * LDP + c + 1] = ll;
            split2(v.z, hh, ll); Wh[r * LDP + c + 2] = hh; Wl[r * LDP + c + 2] = ll;
            split2(v.w, hh, ll); Wh[r * LDP + c + 3] = hh; Wl[r * LDP + c + 3] = ll;
        }
        __syncthreads();

#pragma unroll
        for (int ks = 0; ks < 2; ks++) {
            const int kc = ks * 16;
            uint32_t ah[2][4], al[2][4];
            ldm4(ah[0], sptr(Xh + (arow)      * LDP + kc + acol));
            ldm4(ah[1], sptr(Xh + (arow + 16) * LDP + kc + acol));
            ldm4(al[0], sptr(Xl + (arow)      * LDP + kc + acol));
            ldm4(al[1], sptr(Xl + (arow + 16) * LDP + kc + acol));

            uint32_t bh[4][2], bl[4][2];
            {
                uint32_t t[4];
                ldm4(t, sptr(Wh + (wn * 32 + brow) * LDP + kc + bc8));
                bh[0][0] = t[0]; bh[0][1] = t[1]; bh[1][0] = t[2]; bh[1][1] = t[3];
                ldm4(t, sptr(Wh + (wn * 32 + 16 + brow) * LDP + kc + bc8));
                bh[2][0] = t[0]; bh[2][1] = t[1]; bh[3][0] = t[2]; bh[3][1] = t[3];
                ldm4(t, sptr(Wl + (wn * 32 + brow) * LDP + kc + bc8));
                bl[0][0] = t[0]; bl[0][1] = t[1]; bl[1][0] = t[2]; bl[1][1] = t[3];
                ldm4(t, sptr(Wl + (wn * 32 + 16 + brow) * LDP + kc + bc8));
                bl[2][0] = t[0]; bl[2][1] = t[1]; bl[3][0] = t[2]; bl[3][1] = t[3];
            }
#pragma unroll
            for (int mt = 0; mt < 2; mt++)
#pragma unroll
                for (int nt = 0; nt < 4; nt++) {
                    mma_bf16(acc[mt][nt], ah[mt], bh[nt][0], bh[nt][1]);
                    mma_bf16(acc[mt][nt], ah[mt], bl[nt][0], bl[nt][1]);
                    mma_bf16(acc[mt][nt], al[mt], bh[nt][0], bh[nt][1]);
                }
        }
        __syncthreads();
    }

    // Epilogue
#pragma unroll
    for (int mt = 0; mt < 2; mt++) {
#pragma unroll
        for (int nt = 0; nt < 4; nt++) {
            const int r0 = bm + wm * 32 + mt * 16 + (lane >> 2);
            const int c0 = bn + wn * 32 + nt * 8 + ((lane & 3) << 1);
            if (MODE == 0) {
                *(float2*)(Y + (size_t)r0 * N + c0)       = make_float2(acc[mt][nt][0], acc[mt][nt][1]);
                *(float2*)(Y + (size_t)(r0 + 8) * N + c0) = make_float2(acc[mt][nt][2], acc[mt][nt][3]);
            } else {
                const int b0i = r0 / SS, s0 = r0 % SS;
                const int h0 = c0 / HDD, d0 = c0 % HDD;
                float* p0 = Y + (((size_t)b0i * H + h0) * SS + s0) * HDD + d0;
                *(float2*)p0 = make_float2(acc[mt][nt][0], acc[mt][nt][1]);
                const int r1 = r0 + 8;
                const int b1i = r1 / SS, s1 = r1 % SS;
                float* p1 = Y + (((size_t)b1i * H + h0) * SS + s1) * HDD + d0;
                *(float2*)p1 = make_float2(acc[mt][nt][2], acc[mt][nt][3]);
            }
        }
    }
}

// ---------------------------------------------------------------------------
// In-place RoPE on [B, H, S, HD] (unchanged from R1)
// ---------------------------------------------------------------------------
template <int WHICH>
__global__ void rope_kernel()
{
    const int s = blockIdx.x, h = blockIdx.y, b = blockIdx.z;
    const int d = threadIdx.x;  // 0..63
    const int H = WHICH ? NKVV : NHH;
    float* P = WHICH ? g_K : g_Q;
    const size_t base = (((size_t)b * H + h) * SS + s) * HDD;

    const double inv = pow(10000.0, -(double)d / 64.0);
    const float f = (float)((double)s * inv);
    float sn, c;
    sincosf(f, &sn, &c);

    const float x1 = P[base + d];
    const float x2 = P[base + d + 64];
    P[base + d]      = x1 * c - x2 * sn;
    P[base + d + 64] = x2 * c + x1 * sn;
}

// ---------------------------------------------------------------------------
// Flash attention with bf16-split mma (causal, GQA).
// Q tile 64 x 128, KV tile 32 x 128.  256 threads = 8 warps: 4(M) x 2(N).
// QK phase: warp -> 16 rows x 16 kv.  PV phase: warp -> 16 rows x 64 dims.
// Online softmax in mma-fragment layout; cross-warp row reduce via smem.
// ---------------------------------------------------------------------------
#define LQ 136  // bf16 stride for 128-wide tiles
#define LP 40   // bf16 stride for P (32-wide)

__global__ void __launch_bounds__(256) attn_mma()
{
    extern __shared__ __align__(16) char smraw[];
    __nv_bfloat16* Qh = (__nv_bfloat16*)smraw;       // 64 x LQ
    __nv_bfloat16* Ql = Qh + 64 * LQ;
    __nv_bfloat16* Kh = Ql + 64 * LQ;                // 32 x LQ
    __nv_bfloat16* Kl = Kh + 32 * LQ;
    __nv_bfloat16* Vh = Kl + 32 * LQ;
    __nv_bfloat16* Vl = Vh + 32 * LQ;
    __nv_bfloat16* Ph = Vl + 32 * LQ;                // 64 x LP
    __nv_bfloat16* Pl = Ph + 64 * LP;
    float* row_m     = (float*)(Pl + 64 * LP);
    float* row_l     = row_m + 64;
    float* row_alpha = row_l + 64;
    float* red_max   = row_alpha + 64;   // [2][64]
    float* red_sum   = red_max + 128;    // [2][64]

    const int qt = blockIdx.x, h = blockIdx.y, b = blockIdx.z;
    const int kvh = h >> 2;
    const int tid = threadIdx.x, lane = tid & 31, wid = tid >> 5;
    const int wm = wid & 3, wn = wid >> 2;

    const float* Qg = g_Q + (((size_t)b * NHH + h) * SS + (size_t)qt * 64) * HDD;
    const float* Kg = g_K + ((size_t)b * NKVV + kvh) * SS * HDD;
    const float* Vg = g_V + ((size_t)b * NKVV + kvh) * SS * HDD;

    // Load + split Q tile 64x128
#pragma unroll
    for (int i = 0; i < 8; i++) {
        const int lin = tid + i * 256;
        const int r = lin >> 5, c = (lin & 31) << 2;
        float4 v = *(const float4*)(Qg + (size_t)r * HDD + c);
        __nv_bfloat16 hh, ll;
        split2(v.x, hh, ll); Qh[r * LQ + c + 0] = hh; Ql[r * LQ + c + 0] = ll;
        split2(v.y, hh, ll); Qh[r * LQ + c + 1] = hh; Ql[r * LQ + c + 1] = ll;
        split2(v.z, hh, ll); Qh[r * LQ + c + 2] = hh; Ql[r * LQ + c + 2] = ll;
        split2(v.w, hh, ll); Qh[r * LQ + c + 3] = hh; Ql[r * LQ + c + 3] = ll;
    }
    if (tid < 64) { row_m[tid] = -1e30f; row_l[tid] = 0.0f; }

    float O[8][4];
#pragma unroll
    for (int i = 0; i < 8; i++)
#pragma unroll
        for (int e = 0; e < 4; e++) O[i][e] = 0.0f;

    const float scale = 0.08838834764831845f;  // 1/sqrt(128)
    const int ntiles = 2 * qt + 2;

    // fragment address components
    const int ar  = wm * 16 + (lane & 15);       // QK A rows
    const int ac  = (lane >> 4) << 3;
    const int br  = wn * 16 + (lane & 7) + ((lane & 16) ? 8 : 0);  // K frag rows
    const int bc8 = (lane & 8) ? 8 : 0;
    const int par = wm * 16 + (lane & 15);       // P frag rows
    const int vr  = (lane & 7) + ((lane & 8) ? 8 : 0);             // V frag rows
    const int vc8 = (lane & 16) ? 8 : 0;
    const int rloc = wm * 16 + (lane >> 2);      // softmax row (local)

    for (int t = 0; t < ntiles; t++) {
        const int kv0 = t * 32;
        __syncthreads();   // protect K/V/P smem from previous-iteration readers

        // Load + split K,V tiles 32x128
#pragma unroll
        for (int i = 0; i < 4; i++) {
            const int lin = tid + i * 256;
            const int r = lin >> 5, c = (lin & 31) << 2;
            float4 kv_ = *(const float4*)(Kg + (size_t)(kv0 + r) * HDD + c);
            float4 vv_ = *(const float4*)(Vg + (size_t)(kv0 + r) * HDD + c);
            __nv_bfloat16 hh, ll;
            split2(kv_.x, hh, ll); Kh[r * LQ + c + 0] = hh; Kl[r * LQ + c + 0] = ll;
            split2(kv_.y, hh, ll); Kh[r * LQ + c + 1] = hh; Kl[r * LQ + c + 1] = ll;
            split2(kv_.z, hh, ll); Kh[r * LQ + c + 2] = hh; Kl[r * LQ + c + 2] = ll;
            split2(kv_.w, hh, ll); Kh[r * LQ + c + 3] = hh; Kl[r * LQ + c + 3] = ll;
            split2(vv_.x, hh, ll); Vh[r * LQ + c + 0] = hh; Vl[r * LQ + c + 0] = ll;
            split2(vv_.y, hh, ll); Vh[r * LQ + c + 1] = hh; Vl[r * LQ + c + 1] = ll;
            split2(vv_.z, hh, ll); Vh[r * LQ + c + 2] = hh; Vl[r * LQ + c + 2] = ll;
            split2(vv_.w, hh, ll); Vh[r * LQ + c + 3] = hh; Vl[r * LQ + c + 3] = ll;
        }
        __syncthreads();

        // ---- QK^T: 16 rows x 16 kv per warp ----
        float sc[2][4];
#pragma unroll
        for (int nt = 0; nt < 2; nt++)
#pragma unroll
            for (int e = 0; e < 4; e++) sc[nt][e] = 0.0f;

#pragma unroll
        for (int ks = 0; ks < 8; ks++) {
            uint32_t aq[4], aql[4], bk[4], bkl[4];
            ldm4(aq,  sptr(Qh + ar * LQ + ks * 16 + ac));
            ldm4(aql, sptr(Ql + ar * LQ + ks * 16 + ac));
            ldm4(bk,  sptr(Kh + br * LQ + ks * 16 + bc8));
            ldm4(bkl, sptr(Kl + br * LQ + ks * 16 + bc8));
            mma_bf16(sc[0], aq,  bk[0],  bk[1]);
            mma_bf16(sc[1], aq,  bk[2],  bk[3]);
            mma_bf16(sc[0], aq,  bkl[0], bkl[1]);
            mma_bf16(sc[1], aq,  bkl[2], bkl[3]);
            mma_bf16(sc[0], aql, bk[0],  bk[1]);
            mma_bf16(sc[1], aql, bk[2],  bk[3]);
        }

        // ---- mask + scale ----
        const int grow = qt * 64 + rloc;
        const int gcol = kv0 + wn * 16 + ((lane & 3) << 1);
#pragma unroll
        for (int nt = 0; nt < 2; nt++)
#pragma unroll
            for (int e = 0; e < 4; e++) {
                const int rr = grow + ((e & 2) ? 8 : 0);
                const int cc = gcol + nt * 8 + (e & 1);
                const float s = sc[nt][e] * scale;
                sc[nt][e] = (cc <= rr) ? s : -1e30f;
            }

        // ---- partial row max (quad reduce, then cross-warp via smem) ----
        float m0 = fmaxf(fmaxf(sc[0][0], sc[0][1]), fmaxf(sc[1][0], sc[1][1]));
        float m1 = fmaxf(fmaxf(sc[0][2], sc[0][3]), fmaxf(sc[1][2], sc[1][3]));
        m0 = fmaxf(m0, __shfl_xor_sync(0xffffffffu, m0, 1));
        m0 = fmaxf(m0, __shfl_xor_sync(0xffffffffu, m0, 2));
        m1 = fmaxf(m1, __shfl_xor_sync(0xffffffffu, m1, 1));
        m1 = fmaxf(m1, __shfl_xor_sync(0xffffffffu, m1, 2));
        if ((lane & 3) == 0) {
            red_max[wn * 64 + rloc]     = m0;
            red_max[wn * 64 + rloc + 8] = m1;
        }
        __syncthreads();
        if (tid < 64) {
            const float mo = row_m[tid];
            const float mn = fmaxf(mo, fmaxf(red_max[tid], red_max[64 + tid]));
            row_alpha[tid] = __expf(mo - mn);
            row_m[tid] = mn;
        }
        __syncthreads();

        // ---- P = exp(s - m), write split to smem, partial sums ----
        const float mr0 = row_m[rloc];
        const float mr1 = row_m[rloc + 8];
        float s0 = 0.0f, s1 = 0.0f;
#pragma unroll
        for (int nt = 0; nt < 2; nt++) {
            const float p0 = __expf(sc[nt][0] - mr0);
            const float p1 = __expf(sc[nt][1] - mr0);
            const float p2 = __expf(sc[nt][2] - mr1);
            const float p3 = __expf(sc[nt][3] - mr1);
            s0 += p0 + p1; s1 += p2 + p3;
            const int pc = wn * 16 + nt * 8 + ((lane & 3) << 1);
            __nv_bfloat16 h0, l0, h1, l1;
            split2(p0, h0, l0); split2(p1, h1, l1);
            *(__nv_bfloat162*)(Ph + rloc * LP + pc) = __halves2bfloat162(h0, h1);
            *(__nv_bfloat162*)(Pl + rloc * LP + pc) = __halves2bfloat162(l0, l1);
            split2(p2, h0, l0); split2(p3, h1, l1);
            *(__nv_bfloat162*)(Ph + (rloc + 8) * LP + pc) = __halves2bfloat162(h0, h1);
            *(__nv_bfloat162*)(Pl + (rloc + 8) * LP + pc) = __halves2bfloat162(l0, l1);
        }
        s0 += __shfl_xor_sync(0xffffffffu, s0, 1);
        s0 += __shfl_xor_sync(0xffffffffu, s0, 2);
        s1 += __shfl_xor_sync(0xffffffffu, s1, 1);
        s1 += __shfl_xor_sync(0xffffffffu, s1, 2);
        if ((lane & 3) == 0) {
            red_sum[wn * 64 + rloc]     = s0;
            red_sum[wn * 64 + rloc + 8] = s1;
        }
        __syncthreads();
        if (tid < 64)
            row_l[tid] = row_l[tid] * row_alpha[tid] + red_sum[tid] + red_sum[64 + tid];

        // ---- rescale O, then PV: 16 rows x 64 dims per warp ----
        const float a0 = row_alpha[rloc];
        const float a1 = row_alpha[rloc + 8];
#pragma unroll
        for (int nt = 0; nt < 8; nt++) {
            O[nt][0] *= a0; O[nt][1] *= a0; O[nt][2] *= a1; O[nt][3] *= a1;
        }
#pragma unroll
        for (int ks = 0; ks < 2; ks++) {
            uint32_t ap[4], apl[4];
            ldm4(ap,  sptr(Ph + par * LP + ks * 16 + ac));
            ldm4(apl, sptr(Pl + par * LP + ks * 16 + ac));
#pragma unroll
            for (int g = 0; g < 4; g++) {
                uint32_t bv[4], bvl[4];
                ldm4t(bv,  sptr(Vh + (ks * 16 + vr) * LQ + wn * 64 + g * 16 + vc8));
                ldm4t(bvl, sptr(Vl + (ks * 16 + vr) * LQ + wn * 64 + g * 16 + vc8));
                mma_bf16(O[g * 2 + 0], ap,  bv[0],  bv[1]);
                mma_bf16(O[g * 2 + 1], ap,  bv[2],  bv[3]);
                mma_bf16(O[g * 2 + 0], ap,  bvl[0], bvl[1]);
                mma_bf16(O[g * 2 + 1], ap,  bvl[2], bvl[3]);
                mma_bf16(O[g * 2 + 0], apl, bv[0],  bv[1]);
                mma_bf16(O[g * 2 + 1], apl, bv[2],  bv[3]);
            }
        }
    }

    __syncthreads();
    const float inv0 = 1.0f / row_l[rloc];
    const float inv1 = 1.0f / row_l[rloc + 8];
    float* AO = g_AO + ((size_t)b * SS + (size_t)qt * 64) * HIDD + (size_t)h * HDD;
#pragma unroll
    for (int nt = 0; nt < 8; nt++) {
        const int cc = wn * 64 + nt * 8 + ((lane & 3) << 1);
        *(float2*)(AO + (size_t)rloc * HIDD + cc)       = make_float2(O[nt][0] * inv0, O[nt][1] * inv0);
        *(float2*)(AO + (size_t)(rloc + 8) * HIDD + cc) = make_float2(O[nt][2] * inv1, O[nt][3] * inv1);
    }
}

// ---------------------------------------------------------------------------
extern "C" void kernel_launch(void* const* d_in, const int* in_sizes, int n_in,
                              void* d_out, int out_size)
{
    (void)in_sizes; (void)n_in; (void)out_size;
    const float* hs = (const float*)d_in[0];
    const float* Wq = (const float*)d_in[1];
    const float* Wk = (const float*)d_in[2];
    const float* Wv = (const float*)d_in[3];
    const float* Wo = (const float*)d_in[4];
    float* out = (float*)d_out;

    const int M = BB * SS;  // 4096
    dim3 blk(256);

    // dynamic smem for attention
    const int attn_smem =
        (64 * LQ * 2 + 32 * LQ * 4 + 64 * LP * 2) * (int)sizeof(__nv_bfloat16) +
        (64 * 3 + 128 * 2) * (int)sizeof(float);
    cudaFuncSetAttribute(attn_mma, cudaFuncAttributeMaxDynamicSharedMemorySize, attn_smem);

    // QKV projections (scatter to head-major scratch)
    gemm_mma<1><<<dim3((NHH * HDD) / 64, M / 128), blk>>>(
        hs, Wq, nullptr, M, NHH * HDD, HIDD, NHH, 0, 1);
    gemm_mma<1><<<dim3((NKVV * HDD) / 64, M / 128), blk>>>(
        hs, Wk, nullptr, M, NKVV * HDD, HIDD, NKVV, 0, 2);
    gemm_mma<1><<<dim3((NKVV * HDD) / 64, M / 128), blk>>>(
        hs, Wv, nullptr, M, NKVV * HDD, HIDD, NKVV, 0, 3);

    // RoPE in place on Q and K
    rope_kernel<0><<<dim3(SS, NHH, BB), 64>>>();
    rope_kernel<1><<<dim3(SS, NKVV, BB), 64>>>();

    // Causal GQA flash attention -> g_AO [B, S, HID]
    attn_mma<<<dim3(SS / 64, NHH, BB), blk, attn_smem>>>();

    // Output projection: out = AO @ Wo^T
    gemm_mma<0><<<dim3(HIDD / 64, M / 128), blk>>>(
        nullptr, Wo, out, M, HIDD, HIDD, 0, 1, 0);
}

// round 3
// speedup vs baseline: 2.8515x; 1.0930x over previous
#include <cuda_runtime.h>
#include <cuda_bf16.h>
#include <math.h>
#include <stdint.h>

// Problem constants
#define BB   2
#define SS   2048
#define HIDD 4096
#define NHH  32
#define NKVV 8
#define HDD  128
#define GG   4

#define N_HS ((size_t)BB * SS * HIDD)        // 16,777,216
#define N_WQ ((size_t)HIDD * HIDD)           // 16,777,216
#define N_WK ((size_t)NKVV * HDD * HIDD)     // 4,194,304
#define N_QB ((size_t)BB * NHH * SS * HDD)   // 16,777,216
#define N_KB ((size_t)BB * NKVV * SS * HDD)  // 4,194,304

// fp32 intermediates (pre-RoPE / pre-split)
__device__ float g_Q[N_QB];
__device__ float g_K[N_KB];
__device__ float g_V[N_KB];

// bf16 hi/lo split operands
__device__ __nv_bfloat16 g_hsh[N_HS],  g_hsl[N_HS];
__device__ __nv_bfloat16 g_Wqh[N_WQ],  g_Wql[N_WQ];
__device__ __nv_bfloat16 g_Wkh[N_WK],  g_Wkl[N_WK];
__device__ __nv_bfloat16 g_Wvh[N_WK],  g_Wvl[N_WK];
__device__ __nv_bfloat16 g_Woh[N_WQ],  g_Wol[N_WQ];
__device__ __nv_bfloat16 g_Qbh[N_QB],  g_Qbl[N_QB];   // post-RoPE, pre-scaled
__device__ __nv_bfloat16 g_Kbh[N_KB],  g_Kbl[N_KB];   // post-RoPE
__device__ __nv_bfloat16 g_Vbh[N_KB],  g_Vbl[N_KB];
__device__ __nv_bfloat16 g_AOh[N_HS],  g_AOl[N_HS];   // attention output

// ---------------------------------------------------------------------------
// helpers
// ---------------------------------------------------------------------------
__device__ __forceinline__ uint32_t sptr(const void* p) {
    return (uint32_t)__cvta_generic_to_shared(p);
}
__device__ __forceinline__ void cp16(uint32_t d, const void* s) {
    asm volatile("cp.async.cg.shared.global [%0], [%1], 16;\n" :: "r"(d), "l"(s));
}
__device__ __forceinline__ void cp_commit() { asm volatile("cp.async.commit_group;\n"); }
template <int N> __device__ __forceinline__ void cp_wait() {
    asm volatile("cp.async.wait_group %0;\n" :: "n"(N));
}
__device__ __forceinline__ void ldm4(uint32_t* r, uint32_t a) {
    asm volatile("ldmatrix.sync.aligned.m8n8.x4.shared.b16 {%0,%1,%2,%3}, [%4];\n"
        : "=r"(r[0]), "=r"(r[1]), "=r"(r[2]), "=r"(r[3]) : "r"(a));
}
__device__ __forceinline__ void ldm4t(uint32_t* r, uint32_t a) {
    asm volatile("ldmatrix.sync.aligned.m8n8.x4.trans.shared.b16 {%0,%1,%2,%3}, [%4];\n"
        : "=r"(r[0]), "=r"(r[1]), "=r"(r[2]), "=r"(r[3]) : "r"(a));
}
__device__ __forceinline__ void mma_bf16(float* c, const uint32_t* a, uint32_t b0, uint32_t b1) {
    asm volatile(
        "mma.sync.aligned.m16n8k16.row.col.f32.bf16.bf16.f32 "
        "{%0,%1,%2,%3}, {%4,%5,%6,%7}, {%8,%9}, {%0,%1,%2,%3};\n"
        : "+f"(c[0]), "+f"(c[1]), "+f"(c[2]), "+f"(c[3])
        : "r"(a[0]), "r"(a[1]), "r"(a[2]), "r"(a[3]), "r"(b0), "r"(b1));
}
__device__ __forceinline__ void split2(float x, __nv_bfloat16& h, __nv_bfloat16& l) {
    h = __float2bfloat16(x);
    l = __float2bfloat16(x - __bfloat162float(h));
}

// ---------------------------------------------------------------------------
// Elementwise fp32 -> bf16 hi/lo split.  dsel picks the destination pair;
// src==nullptr means read internal g_V.  4 elems / thread.
// ---------------------------------------------------------------------------
__global__ void __launch_bounds__(256) split_kernel(const float* __restrict__ src,
                                                    int dsel, size_t n)
{
    __nv_bfloat16 *dh, *dl;
    switch (dsel) {
        case 0: dh = g_hsh; dl = g_hsl; break;
        case 1: dh = g_Wqh; dl = g_Wql; break;
        case 2: dh = g_Wkh; dl = g_Wkl; break;
        case 3: dh = g_Wvh; dl = g_Wvl; break;
        case 4: dh = g_Woh; dl = g_Wol; break;
        default: dh = g_Vbh; dl = g_Vbl; src = g_V; break;
    }
    const size_t i = ((size_t)blockIdx.x * 256 + threadIdx.x) * 4;
    if (i >= n) return;
    float4 v = *(const float4*)(src + i);
    __nv_bfloat16 h0, l0, h1, l1, h2, l2, h3, l3;
    split2(v.x, h0, l0); split2(v.y, h1, l1);
    split2(v.z, h2, l2); split2(v.w, h3, l3);
    ushort4 uh, ul;
    uh.x = __bfloat16_as_ushort(h0); uh.y = __bfloat16_as_ushort(h1);
    uh.z = __bfloat16_as_ushort(h2); uh.w = __bfloat16_as_ushort(h3);
    ul.x = __bfloat16_as_ushort(l0); ul.y = __bfloat16_as_ushort(l1);
    ul.z = __bfloat16_as_ushort(l2); ul.w = __bfloat16_as_ushort(l3);
    *(ushort4*)(dh + i) = uh;
    *(ushort4*)(dl + i) = ul;
}

// ---------------------------------------------------------------------------
// RoPE + split.  WHICH 0: Q (also folds 1/sqrt(HD)), 1: K.
// ---------------------------------------------------------------------------
template <int WHICH>
__global__ void rope_split_kernel()
{
    const int s = blockIdx.x, h = blockIdx.y, b = blockIdx.z;
    const int d = threadIdx.x;  // 0..63
    const int H = WHICH ? NKVV : NHH;
    const float* P = WHICH ? g_K : g_Q;
    __nv_bfloat16* Dh = WHICH ? g_Kbh : g_Qbh;
    __nv_bfloat16* Dl = WHICH ? g_Kbl : g_Qbl;
    const size_t base = (((size_t)b * H + h) * SS + s) * HDD;

    const double inv = pow(10000.0, -(double)d / 64.0);
    const float f = (float)((double)s * inv);
    float sn, c;
    sincosf(f, &sn, &c);

    const float x1 = P[base + d];
    const float x2 = P[base + d + 64];
    float y1 = x1 * c - x2 * sn;
    float y2 = x2 * c + x1 * sn;
    if (WHICH == 0) { y1 *= 0.08838834764831845f; y2 *= 0.08838834764831845f; }
    __nv_bfloat16 hh, ll;
    split2(y1, hh, ll); Dh[base + d] = hh;      Dl[base + d] = ll;
    split2(y2, hh, ll); Dh[base + d + 64] = hh; Dl[base + d + 64] = ll;
}

// ---------------------------------------------------------------------------
// Pipelined NT GEMM on pre-split bf16: Y = Xh*Wh^T + Xh*Wl^T + Xl*Wh^T.
// Block 128(M) x 64(N), K-step 32, 2-stage cp.async double buffer.
// 8 warps 4(M)x2(N), warp tile 32x32.
// MODE 0: fp32 row-major out.  MODE 1: fp32 scatter to [B,H,S,HD].
// xsel: 0 -> hs split, 1 -> AO split.  wsel: 0..3 -> Wq,Wk,Wv,Wo.
// dsel (MODE1): 1 g_Q, 2 g_K, 3 g_V.
// ---------------------------------------------------------------------------
#define LDP 40
#define GSTAGE (128 * LDP + 128 * LDP / 2)   // Xh+Xl (5120*2? no) — computed below

// per-stage element counts
#define XS_ELEM (128 * LDP)   // 5120
#define WS_ELEM (64 * LDP)    // 2560
#define STAGE_ELEM (2 * XS_ELEM + 2 * WS_ELEM)  // 15360
#define GEMM_SMEM (2 * STAGE_ELEM * 2)          // bytes = 61440

template <int MODE>
__global__ void __launch_bounds__(256) gemm_bf3(
    int xsel, int wsel, int dsel, float* __restrict__ Yext,
    int M, int N, int K, int H)
{
    extern __shared__ __align__(16) __nv_bfloat16 sm[];

    const __nv_bfloat16 *Xh_g, *Xl_g, *Wh_g, *Wl_g;
    if (xsel == 0) { Xh_g = g_hsh; Xl_g = g_hsl; }
    else           { Xh_g = g_AOh; Xl_g = g_AOl; }
    if (wsel == 0)      { Wh_g = g_Wqh; Wl_g = g_Wql; }
    else if (wsel == 1) { Wh_g = g_Wkh; Wl_g = g_Wkl; }
    else if (wsel == 2) { Wh_g = g_Wvh; Wl_g = g_Wvl; }
    else                { Wh_g = g_Woh; Wl_g = g_Wol; }
    float* Y;
    if (MODE == 1) Y = (dsel == 1) ? g_Q : (dsel == 2) ? g_K : g_V;
    else           Y = Yext;

    const int bm = blockIdx.y * 128;
    const int bn = blockIdx.x * 64;
    const int tid = threadIdx.x;
    const int lane = tid & 31;
    const int wid = tid >> 5;
    const int wm = wid & 3;
    const int wn = wid >> 2;

    float acc[2][4][4];
#pragma unroll
    for (int i = 0; i < 2; i++)
#pragma unroll
        for (int j = 0; j < 4; j++)
#pragma unroll
            for (int e = 0; e < 4; e++) acc[i][j][e] = 0.0f;

    // loader indices: X chunk id -> row=id>>2, col8=(id&3)*8 ; 512 chunks/array
    const int xr0 = tid >> 2, xc0 = (tid & 3) << 3;
    const int xr1 = (tid + 256) >> 2, xc1 = ((tid + 256) & 3) << 3;
    const int wr = tid >> 2, wc = (tid & 3) << 3;   // 256 chunks/array

    const int nk = K / 32;

    auto load_stage = [&](int stage, int k0) {
        __nv_bfloat16* Xh = sm + (size_t)stage * STAGE_ELEM;
        __nv_bfloat16* Xl = Xh + XS_ELEM;
        __nv_bfloat16* Wh = Xl + XS_ELEM;
        __nv_bfloat16* Wl = Wh + WS_ELEM;
        cp16(sptr(Xh + xr0 * LDP + xc0), Xh_g + (size_t)(bm + xr0) * K + k0 + xc0);
        cp16(sptr(Xh + xr1 * LDP + xc1), Xh_g + (size_t)(bm + xr1) * K + k0 + xc1);
        cp16(sptr(Xl + xr0 * LDP + xc0), Xl_g + (size_t)(bm + xr0) * K + k0 + xc0);
        cp16(sptr(Xl + xr1 * LDP + xc1), Xl_g + (size_t)(bm + xr1) * K + k0 + xc1);
        if (tid < 256) {
            cp16(sptr(Wh + wr * LDP + wc), Wh_g + (size_t)(bn + wr) * K + k0 + wc);
            cp16(sptr(Wl + wr * LDP + wc), Wl_g + (size_t)(bn + wr) * K + k0 + wc);
        }
        cp_commit();
    };

    load_stage(0, 0);

    const int arow = wm * 32 + (lane & 15);
    const int acol = (lane >> 4) << 3;
    const int brow = wn * 32 + (lane & 7) + ((lane & 16) ? 8 : 0);
    const int bc8  = (lane & 8) ? 8 : 0;

    for (int kt = 0; kt < nk; kt++) {
        const int cur = kt & 1;
        if (kt + 1 < nk) load_stage(cur ^ 1, (kt + 1) * 32);
        if (kt + 1 < nk) cp_wait<1>(); else cp_wait<0>();
        __syncthreads();

        __nv_bfloat16* Xh = sm + (size_t)cur * STAGE_ELEM;
        __nv_bfloat16* Xl = Xh + XS_ELEM;
        __nv_bfloat16* Wh = Xl + XS_ELEM;
        __nv_bfloat16* Wl = Wh + WS_ELEM;

#pragma unroll
        for (int ks = 0; ks < 2; ks++) {
            const int kc = ks * 16;
            uint32_t ah[2][4], al[2][4];
            ldm4(ah[0], sptr(Xh + (arow)      * LDP + kc + acol));
            ldm4(ah[1], sptr(Xh + (arow + 16) * LDP + kc + acol));
            ldm4(al[0], sptr(Xl + (arow)      * LDP + kc + acol));
            ldm4(al[1], sptr(Xl + (arow + 16) * LDP + kc + acol));

            uint32_t bh[4][2], bl[4][2];
            {
                uint32_t t[4];
                ldm4(t, sptr(Wh + brow * LDP + kc + bc8));
                bh[0][0] = t[0]; bh[0][1] = t[1]; bh[1][0] = t[2]; bh[1][1] = t[3];
                ldm4(t, sptr(Wh + (brow + 16) * LDP + kc + bc8));
                bh[2][0] = t[0]; bh[2][1] = t[1]; bh[3][0] = t[2]; bh[3][1] = t[3];
                ldm4(t, sptr(Wl + brow * LDP + kc + bc8));
                bl[0][0] = t[0]; bl[0][1] = t[1]; bl[1][0] = t[2]; bl[1][1] = t[3];
                ldm4(t, sptr(Wl + (brow + 16) * LDP + kc + bc8));
                bl[2][0] = t[0]; bl[2][1] = t[1]; bl[3][0] = t[2]; bl[3][1] = t[3];
            }
#pragma unroll
            for (int mt = 0; mt < 2; mt++)
#pragma unroll
                for (int nt = 0; nt < 4; nt++) {
                    mma_bf16(acc[mt][nt], ah[mt], bh[nt][0], bh[nt][1]);
                    mma_bf16(acc[mt][nt], ah[mt], bl[nt][0], bl[nt][1]);
                    mma_bf16(acc[mt][nt], al[mt], bh[nt][0], bh[nt][1]);
                }
        }
        __syncthreads();
    }

#pragma unroll
    for (int mt = 0; mt < 2; mt++) {
#pragma unroll
        for (int nt = 0; nt < 4; nt++) {
            const int r0 = bm + wm * 32 + mt * 16 + (lane >> 2);
            const int c0 = bn + wn * 32 + nt * 8 + ((lane & 3) << 1);
            if (MODE == 0) {
                *(float2*)(Y + (size_t)r0 * N + c0)       = make_float2(acc[mt][nt][0], acc[mt][nt][1]);
                *(float2*)(Y + (size_t)(r0 + 8) * N + c0) = make_float2(acc[mt][nt][2], acc[mt][nt][3]);
            } else {
                const int b0i = r0 / SS, s0 = r0 % SS;
                const int h0 = c0 / HDD, d0 = c0 % HDD;
                float* p0 = Y + (((size_t)b0i * H + h0) * SS + s0) * HDD + d0;
                *(float2*)p0 = make_float2(acc[mt][nt][0], acc[mt][nt][1]);
                const int r1 = r0 + 8;
                const int b1i = r1 / SS, s1 = r1 % SS;
                float* p1 = Y + (((size_t)b1i * H + h0) * SS + s1) * HDD + d0;
                *(float2*)p1 = make_float2(acc[mt][nt][2], acc[mt][nt][3]);
            }
        }
    }
}

// ---------------------------------------------------------------------------
// Flash attention (bf16-split mma, causal, GQA) on pre-split Q/K/V.
// Same structure as R2 but bf16 direct loads and split AO epilogue.
// ---------------------------------------------------------------------------
#define LQ 136
#define LP 40

__global__ void __launch_bounds__(256) attn_mma()
{
    extern __shared__ __align__(16) char smraw[];
    __nv_bfloat16* Qh = (__nv_bfloat16*)smraw;       // 64 x LQ
    __nv_bfloat16* Ql = Qh + 64 * LQ;
    __nv_bfloat16* Kh = Ql + 64 * LQ;                // 32 x LQ
    __nv_bfloat16* Kl = Kh + 32 * LQ;
    __nv_bfloat16* Vh = Kl + 32 * LQ;
    __nv_bfloat16* Vl = Vh + 32 * LQ;
    __nv_bfloat16* Ph = Vl + 32 * LQ;                // 64 x LP
    __nv_bfloat16* Pl = Ph + 64 * LP;
    float* row_m     = (float*)(Pl + 64 * LP);
    float* row_l     = row_m + 64;
    float* row_alpha = row_l + 64;
    float* red_max   = row_alpha + 64;   // [2][64]
    float* red_sum   = red_max + 128;    // [2][64]

    const int qt = blockIdx.x, h = blockIdx.y, b = blockIdx.z;
    const int kvh = h >> 2;
    const int tid = threadIdx.x, lane = tid & 31, wid = tid >> 5;
    const int wm = wid & 3, wn = wid >> 2;

    const size_t qoff  = (((size_t)b * NHH + h) * SS + (size_t)qt * 64) * HDD;
    const size_t kvoff = ((size_t)b * NKVV + kvh) * SS * HDD;

    // Load Q tile 64x128 (hi/lo), 16B chunks
#pragma unroll
    for (int j = 0; j < 4; j++) {
        const int i = tid + j * 256;
        const int r = i >> 4, c = (i & 15) << 3;
        *(uint4*)&Qh[r * LQ + c] = *(const uint4*)(g_Qbh + qoff + (size_t)r * HDD + c);
        *(uint4*)&Ql[r * LQ + c] = *(const uint4*)(g_Qbl + qoff + (size_t)r * HDD + c);
    }
    if (tid < 64) { row_m[tid] = -1e30f; row_l[tid] = 0.0f; }

    float O[8][4];
#pragma unroll
    for (int i = 0; i < 8; i++)
#pragma unroll
        for (int e = 0; e < 4; e++) O[i][e] = 0.0f;

    const int ntiles = 2 * qt + 2;

    const int ar  = wm * 16 + (lane & 15);
    const int ac  = (lane >> 4) << 3;
    const int br  = wn * 16 + (lane & 7) + ((lane & 16) ? 8 : 0);
    const int bc8 = (lane & 8) ? 8 : 0;
    const int par = wm * 16 + (lane & 15);
    const int vr  = (lane & 7) + ((lane & 8) ? 8 : 0);
    const int vc8 = (lane & 16) ? 8 : 0;
    const int rloc = wm * 16 + (lane >> 2);

    for (int t = 0; t < ntiles; t++) {
        const int kv0 = t * 32;
        __syncthreads();

        // Load K,V tiles 32x128 hi/lo
#pragma unroll
        for (int j = 0; j < 2; j++) {
            const int i = tid + j * 256;
            const int r = i >> 4, c = (i & 15) << 3;
            const size_t go = kvoff + (size_t)(kv0 + r) * HDD + c;
            *(uint4*)&Kh[r * LQ + c] = *(const uint4*)(g_Kbh + go);
            *(uint4*)&Kl[r * LQ + c] = *(const uint4*)(g_Kbl + go);
            *(uint4*)&Vh[r * LQ + c] = *(const uint4*)(g_Vbh + go);
            *(uint4*)&Vl[r * LQ + c] = *(const uint4*)(g_Vbl + go);
        }
        __syncthreads();

        // ---- QK^T ----
        float sc[2][4];
#pragma unroll
        for (int nt = 0; nt < 2; nt++)
#pragma unroll
            for (int e = 0; e < 4; e++) sc[nt][e] = 0.0f;

#pragma unroll
        for (int ks = 0; ks < 8; ks++) {
            uint32_t aq[4], aql[4], bk[4], bkl[4];
            ldm4(aq,  sptr(Qh + ar * LQ + ks * 16 + ac));
            ldm4(aql, sptr(Ql + ar * LQ + ks * 16 + ac));
            ldm4(bk,  sptr(Kh + br * LQ + ks * 16 + bc8));
            ldm4(bkl, sptr(Kl + br * LQ + ks * 16 + bc8));
            mma_bf16(sc[0], aq,  bk[0],  bk[1]);
            mma_bf16(sc[1], aq,  bk[2],  bk[3]);
            mma_bf16(sc[0], aq,  bkl[0], bkl[1]);
            mma_bf16(sc[1], aq,  bkl[2], bkl[3]);
            mma_bf16(sc[0], aql, bk[0],  bk[1]);
            mma_bf16(sc[1], aql, bk[2],  bk[3]);
        }

        // ---- causal mask (scores pre-scaled via Q) ----
        const int grow = qt * 64 + rloc;
        const int gcol = kv0 + wn * 16 + ((lane & 3) << 1);
#pragma unroll
        for (int nt = 0; nt < 2; nt++)
#pragma unroll
            for (int e = 0; e < 4; e++) {
                const int rr = grow + ((e & 2) ? 8 : 0);
                const int cc = gcol + nt * 8 + (e & 1);
                sc[nt][e] = (cc <= rr) ? sc[nt][e] : -1e30f;
            }

        // ---- row max ----
        float m0 = fmaxf(fmaxf(sc[0][0], sc[0][1]), fmaxf(sc[1][0], sc[1][1]));
        float m1 = fmaxf(fmaxf(sc[0][2], sc[0][3]), fmaxf(sc[1][2], sc[1][3]));
        m0 = fmaxf(m0, __shfl_xor_sync(0xffffffffu, m0, 1));
        m0 = fmaxf(m0, __shfl_xor_sync(0xffffffffu, m0, 2));
        m1 = fmaxf(m1, __shfl_xor_sync(0xffffffffu, m1, 1));
        m1 = fmaxf(m1, __shfl_xor_sync(0xffffffffu, m1, 2));
        if ((lane & 3) == 0) {
            red_max[wn * 64 + rloc]     = m0;
            red_max[wn * 64 + rloc + 8] = m1;
        }
        __syncthreads();
        if (tid < 64) {
            const float mo = row_m[tid];
            const float mn = fmaxf(mo, fmaxf(red_max[tid], red_max[64 + tid]));
            row_alpha[tid] = __expf(mo - mn);
            row_m[tid] = mn;
        }
        __syncthreads();

        // ---- P = exp(s-m), split to smem, partial sums ----
        const float mr0 = row_m[rloc];
        const float mr1 = row_m[rloc + 8];
        float s0 = 0.0f, s1 = 0.0f;
#pragma unroll
        for (int nt = 0; nt < 2; nt++) {
            const float p0 = __expf(sc[nt][0] - mr0);
            const float p1 = __expf(sc[nt][1] - mr0);
            const float p2 = __expf(sc[nt][2] - mr1);
            const float p3 = __expf(sc[nt][3] - mr1);
            s0 += p0 + p1; s1 += p2 + p3;
            const int pc = wn * 16 + nt * 8 + ((lane & 3) << 1);
            __nv_bfloat16 h0, l0, h1, l1;
            split2(p0, h0, l0); split2(p1, h1, l1);
            *(__nv_bfloat162*)(Ph + rloc * LP + pc) = __halves2bfloat162(h0, h1);
            *(__nv_bfloat162*)(Pl + rloc * LP + pc) = __halves2bfloat162(l0, l1);
            split2(p2, h0, l0); split2(p3, h1, l1);
            *(__nv_bfloat162*)(Ph + (rloc + 8) * LP + pc) = __halves2bfloat162(h0, h1);
            *(__nv_bfloat162*)(Pl + (rloc + 8) * LP + pc) = __halves2bfloat162(l0, l1);
        }
        s0 += __shfl_xor_sync(0xffffffffu, s0, 1);
        s0 += __shfl_xor_sync(0xffffffffu, s0, 2);
        s1 += __shfl_xor_sync(0xffffffffu, s1, 1);
        s1 += __shfl_xor_sync(0xffffffffu, s1, 2);
        if ((lane & 3) == 0) {
            red_sum[wn * 64 + rloc]     = s0;
            red_sum[wn * 64 + rloc + 8] = s1;
        }
        __syncthreads();
        if (tid < 64)
            row_l[tid] = row_l[tid] * row_alpha[tid] + red_sum[tid] + red_sum[64 + tid];

        // ---- rescale O, PV ----
        const float a0 = row_alpha[rloc];
        const float a1 = row_alpha[rloc + 8];
#pragma unroll
        for (int nt = 0; nt < 8; nt++) {
            O[nt][0] *= a0; O[nt][1] *= a0; O[nt][2] *= a1; O[nt][3] *= a1;
        }
#pragma unroll
        for (int ks = 0; ks < 2; ks++) {
            uint32_t ap[4], apl[4];
            ldm4(ap,  sptr(Ph + par * LP + ks * 16 + ac));
            ldm4(apl, sptr(Pl + par * LP + ks * 16 + ac));
#pragma unroll
            for (int g = 0; g < 4; g++) {
                uint32_t bv[4], bvl[4];
                ldm4t(bv,  sptr(Vh + (ks * 16 + vr) * LQ + wn * 64 + g * 16 + vc8));
                ldm4t(bvl, sptr(Vl + (ks * 16 + vr) * LQ + wn * 64 + g * 16 + vc8));
                mma_bf16(O[g * 2 + 0], ap,  bv[0],  bv[1]);
                mma_bf16(O[g * 2 + 1], ap,  bv[2],  bv[3]);
                mma_bf16(O[g * 2 + 0], ap,  bvl[0], bvl[1]);
                mma_bf16(O[g * 2 + 1], ap,  bvl[2], bvl[3]);
                mma_bf16(O[g * 2 + 0], apl, bv[0],  bv[1]);
                mma_bf16(O[g * 2 + 1], apl, bv[2],  bv[3]);
            }
        }
    }

    __syncthreads();
    const float inv0 = 1.0f / row_l[rloc];
    const float inv1 = 1.0f / row_l[rloc + 8];
    const size_t ao = ((size_t)b * SS + (size_t)qt * 64) * HIDD + (size_t)h * HDD;
#pragma unroll
    for (int nt = 0; nt < 8; nt++) {
        const int cc = wn * 64 + nt * 8 + ((lane & 3) << 1);
        __nv_bfloat16 h0, l0, h1, l1;
        split2(O[nt][0] * inv0, h0, l0); split2(O[nt][1] * inv0, h1, l1);
        *(__nv_bfloat162*)(g_AOh + ao + (size_t)rloc * HIDD + cc) = __halves2bfloat162(h0, h1);
        *(__nv_bfloat162*)(g_AOl + ao + (size_t)rloc * HIDD + cc) = __halves2bfloat162(l0, l1);
        split2(O[nt][2] * inv1, h0, l0); split2(O[nt][3] * inv1, h1, l1);
        *(__nv_bfloat162*)(g_AOh + ao + (size_t)(rloc + 8) * HIDD + cc) = __halves2bfloat162(h0, h1);
        *(__nv_bfloat162*)(g_AOl + ao + (size_t)(rloc + 8) * HIDD + cc) = __halves2bfloat162(l0, l1);
    }
}

// ---------------------------------------------------------------------------
extern "C" void kernel_launch(void* const* d_in, const int* in_sizes, int n_in,
                              void* d_out, int out_size)
{
    (void)in_sizes; (void)n_in; (void)out_size;
    const float* hs = (const float*)d_in[0];
    const float* Wq = (const float*)d_in[1];
    const float* Wk = (const float*)d_in[2];
    const float* Wv = (const float*)d_in[3];
    const float* Wo = (const float*)d_in[4];
    float* out = (float*)d_out;

    const int M = BB * SS;  // 4096
    dim3 blk(256);

    const int attn_smem =
        (64 * LQ * 2 + 32 * LQ * 4 + 64 * LP * 2) * (int)sizeof(__nv_bfloat16) +
        (64 * 3 + 128 * 2) * (int)sizeof(float);
    cudaFuncSetAttribute(attn_mma, cudaFuncAttributeMaxDynamicSharedMemorySize, attn_smem);
    cudaFuncSetAttribute(gemm_bf3<0>, cudaFuncAttributeMaxDynamicSharedMemorySize, GEMM_SMEM);
    cudaFuncSetAttribute(gemm_bf3<1>, cudaFuncAttributeMaxDynamicSharedMemorySize, GEMM_SMEM);

    // Split inputs to bf16 hi/lo
    split_kernel<<<(unsigned)(N_HS / 1024), blk>>>(hs, 0, N_HS);
    split_kernel<<<(unsigned)(N_WQ / 1024), blk>>>(Wq, 1, N_WQ);
    split_kernel<<<(unsigned)(N_WK / 1024), blk>>>(Wk, 2, N_WK);
    split_kernel<<<(unsigned)(N_WK / 1024), blk>>>(Wv, 3, N_WK);
    split_kernel<<<(unsigned)(N_WQ / 1024), blk>>>(Wo, 4, N_WQ);

    // QKV projections (fp32 scatter to head-major scratch)
    gemm_bf3<1><<<dim3((NHH * HDD) / 64, M / 128), blk, GEMM_SMEM>>>(
        0, 0, 1, nullptr, M, NHH * HDD, HIDD, NHH);
    gemm_bf3<1><<<dim3((NKVV * HDD) / 64, M / 128), blk, GEMM_SMEM>>>(
        0, 1, 2, nullptr, M, NKVV * HDD, HIDD, NKVV);
    gemm_bf3<1><<<dim3((NKVV * HDD) / 64, M / 128), blk, GEMM_SMEM>>>(
        0, 2, 3, nullptr, M, NKVV * HDD, HIDD, NKVV);

    // RoPE + split for Q/K; plain split for V
    rope_split_kernel<0><<<dim3(SS, NHH, BB), 64>>>();
    rope_split_kernel<1><<<dim3(SS, NKVV, BB), 64>>>();
    split_kernel<<<(unsigned)(N_KB / 1024), blk>>>(nullptr, 5, N_KB);

    // Causal GQA flash attention -> g_AOh/g_AOl
    attn_mma<<<dim3(SS / 64, NHH, BB), blk, attn_smem>>>();

    // Output projection
    gemm_bf3<0><<<dim3(HIDD / 64, M / 128), blk, GEMM_SMEM>>>(
        1, 3, 0, out, M, HIDD, HIDD, 0);
}